// round 1
// baseline (speedup 1.0000x reference)
#include <cuda_runtime.h>
#include <cstdint>

#define S_   32
#define IN_  2048
#define OUT_ 2048
#define TPB  256

// ---------------------------------------------------------------------------
// threefry2x32 (JAX/Random123): 20 rounds, rotations {13,15,26,6}/{17,29,16,24}
// ---------------------------------------------------------------------------
__host__ __device__ __forceinline__ uint32_t rotl32(uint32_t x, int r) {
#ifdef __CUDA_ARCH__
    return __funnelshift_l(x, x, r);
#else
    return (x << r) | (x >> (32 - r));
#endif
}

__host__ __device__ __forceinline__ void tf_round(uint32_t& x0, uint32_t& x1, int r) {
    x0 += x1;
    x1 = rotl32(x1, r);
    x1 ^= x0;
}

__host__ __device__ __forceinline__ void threefry2x32(
    uint32_t k0, uint32_t k1, uint32_t c0, uint32_t c1,
    uint32_t& o0, uint32_t& o1)
{
    const uint32_t k2 = k0 ^ k1 ^ 0x1BD11BDAu;
    uint32_t x0 = c0 + k0;
    uint32_t x1 = c1 + k1;

    tf_round(x0, x1, 13); tf_round(x0, x1, 15); tf_round(x0, x1, 26); tf_round(x0, x1, 6);
    x0 += k1; x1 += k2 + 1u;
    tf_round(x0, x1, 17); tf_round(x0, x1, 29); tf_round(x0, x1, 16); tf_round(x0, x1, 24);
    x0 += k2; x1 += k0 + 2u;
    tf_round(x0, x1, 13); tf_round(x0, x1, 15); tf_round(x0, x1, 26); tf_round(x0, x1, 6);
    x0 += k0; x1 += k1 + 3u;
    tf_round(x0, x1, 17); tf_round(x0, x1, 29); tf_round(x0, x1, 16); tf_round(x0, x1, 24);
    x0 += k1; x1 += k2 + 4u;
    tf_round(x0, x1, 13); tf_round(x0, x1, 15); tf_round(x0, x1, 26); tf_round(x0, x1, 6);
    x0 += k2; x1 += k0 + 5u;

    o0 = x0; o1 = x1;
}

// ---------------------------------------------------------------------------
// bits -> N(0,1) matching jax.random.normal (f32):
//   f = bitcast(bits>>9 | 0x3f800000) - 1            in [0,1)
//   u = f*(1 - lo) + lo,  lo = nextafter(-1,0);  (1-lo) rounds to exactly 2.0f
//   eps = sqrt(2) * erfinv(u), XLA Giles-2012 single-precision polynomial,
//   w = -log1p(-u*u): u*u rounded first, 1-t exact (Sterbenz), __logf ~2ulp.
// ---------------------------------------------------------------------------
__device__ __forceinline__ float bits_to_normal(uint32_t bits) {
    float f = __uint_as_float((bits >> 9) | 0x3f800000u) - 1.0f;
    float u = __fadd_rn(__fmul_rn(f, 2.0f), -0.99999994f);

    float t = __fmul_rn(u, u);
    float w = -__logf(__fadd_rn(1.0f, -t));
    float p;
    if (w < 5.0f) {
        w -= 2.5f;
        p = 2.81022636e-08f;
        p = __fmaf_rn(p, w, 3.43273939e-07f);
        p = __fmaf_rn(p, w, -3.5233877e-06f);
        p = __fmaf_rn(p, w, -4.39150654e-06f);
        p = __fmaf_rn(p, w, 0.00021858087f);
        p = __fmaf_rn(p, w, -0.00125372503f);
        p = __fmaf_rn(p, w, -0.00417768164f);
        p = __fmaf_rn(p, w, 0.246640727f);
        p = __fmaf_rn(p, w, 1.50140941f);
    } else {
        w = __fsqrt_rn(w) - 3.0f;
        p = -0.000200214257f;
        p = __fmaf_rn(p, w, 0.000100950558f);
        p = __fmaf_rn(p, w, 0.00134934322f);
        p = __fmaf_rn(p, w, -0.00367342844f);
        p = __fmaf_rn(p, w, 0.00573950773f);
        p = __fmaf_rn(p, w, -0.0076224613f);
        p = __fmaf_rn(p, w, 0.00943887047f);
        p = __fmaf_rn(p, w, 1.00167406f);
        p = __fmaf_rn(p, w, 2.83297682f);
    }
    return 1.41421354f * __fmul_rn(p, u);   // float32(sqrt(2)) * (p*u)
}

// ---------------------------------------------------------------------------
// One block per output column o. 256 threads stride the IN dimension.
// Per (o,i): one mu/sigma load feeds 32 samples' normals.
// Partitionable threefry: bits[idx] = xor(threefry(key, (0, idx))),
//   idx = s*OUT*IN + o*IN + i = (s<<22) + base.
// ---------------------------------------------------------------------------
__global__ void __launch_bounds__(TPB)
bayes_linear_kernel(const float* __restrict__ x,
                    const float* __restrict__ wmu,
                    const float* __restrict__ wsig,
                    const float* __restrict__ bmu,
                    const float* __restrict__ bsig,
                    float* __restrict__ out,
                    uint32_t wk0, uint32_t wk1,
                    uint32_t bk0, uint32_t bk1)
{
    __shared__ float xs[S_][TPB];

    const int o   = blockIdx.x;
    const int tid = threadIdx.x;

    float acc[S_];
#pragma unroll
    for (int s = 0; s < S_; ++s) acc[s] = 0.0f;

    for (int ii = 0; ii < IN_ / TPB; ++ii) {
        const int i = ii * TPB + tid;

        __syncthreads();   // protect xs reuse from previous iteration
#pragma unroll
        for (int s = 0; s < S_; ++s)
            xs[s][tid] = x[s * IN_ + i];
        __syncthreads();

        const float    mu   = wmu[o * IN_ + i];
        const float    sg   = wsig[o * IN_ + i];
        const uint32_t base = (uint32_t)(o * IN_ + i);

#pragma unroll 4
        for (int s = 0; s < S_; ++s) {
            uint32_t r0, r1;
            threefry2x32(wk0, wk1, 0u, ((uint32_t)s << 22) + base, r0, r1);
            const float e = bits_to_normal(r0 ^ r1);
            acc[s] = __fmaf_rn(__fmaf_rn(sg, e, mu), xs[s][tid], acc[s]);
        }
    }

    __syncthreads();
#pragma unroll
    for (int s = 0; s < S_; ++s) xs[s][tid] = acc[s];
    __syncthreads();

    for (int off = TPB / 2; off >= 8; off >>= 1) {
        if (tid < off) {
#pragma unroll
            for (int s = 0; s < S_; ++s)
                xs[s][tid] += xs[s][tid + off];
        }
        __syncthreads();
    }

    if (tid < S_) {
        float tot = 0.0f;
#pragma unroll
        for (int r = 0; r < 8; ++r) tot += xs[tid][r];

        // bias epsilon: idx = s*OUT + o over bkey
        uint32_t r0, r1;
        threefry2x32(bk0, bk1, 0u, (uint32_t)(tid * OUT_ + o), r0, r1);
        const float eb = bits_to_normal(r0 ^ r1);
        out[tid * OUT_ + o] = tot + __fmaf_rn(bsig[o], eb, bmu[o]);
    }
}

// ---------------------------------------------------------------------------
// kernel_launch: derive the two fold-like subkeys of jax.random.key(42) on the
// host (pure arithmetic — no CUDA API calls), then launch. Graph-capturable.
// ---------------------------------------------------------------------------
extern "C" void kernel_launch(void* const* d_in, const int* in_sizes, int n_in,
                              void* d_out, int out_size)
{
    const float* x    = (const float*)d_in[0];
    const float* wmu  = (const float*)d_in[1];
    const float* wsig = (const float*)d_in[2];
    const float* bmu  = (const float*)d_in[3];
    const float* bsig = (const float*)d_in[4];
    float* out        = (float*)d_out;

    // jax.random.key(42) -> (0, 42); split (fold-like / partitionable):
    //   wkey = threefry(key, (0,0)), bkey = threefry(key, (0,1))
    uint32_t wk0, wk1, bk0, bk1;
    threefry2x32(0u, 42u, 0u, 0u, wk0, wk1);
    threefry2x32(0u, 42u, 0u, 1u, bk0, bk1);

    bayes_linear_kernel<<<OUT_, TPB>>>(x, wmu, wsig, bmu, bsig, out,
                                       wk0, wk1, bk0, bk1);
}

// round 2
// speedup vs baseline: 1.0167x; 1.0167x over previous
#include <cuda_runtime.h>
#include <cstdint>

#define S_   32
#define IN_  2048
#define OUT_ 2048
#define TPB  256

// ---------------------------------------------------------------------------
// Host-side threefry2x32 (for deriving subkeys of jax.random.key(42) only)
// ---------------------------------------------------------------------------
static inline uint32_t h_rotl32(uint32_t x, int r) {
    return (x << r) | (x >> (32 - r));
}
static inline void h_round(uint32_t& x0, uint32_t& x1, int r) {
    x0 += x1; x1 = h_rotl32(x1, r); x1 ^= x0;
}
static void h_threefry2x32(uint32_t k0, uint32_t k1, uint32_t c0, uint32_t c1,
                           uint32_t& o0, uint32_t& o1)
{
    const uint32_t k2 = k0 ^ k1 ^ 0x1BD11BDAu;
    uint32_t x0 = c0 + k0, x1 = c1 + k1;
    h_round(x0,x1,13); h_round(x0,x1,15); h_round(x0,x1,26); h_round(x0,x1,6);
    x0 += k1; x1 += k2 + 1u;
    h_round(x0,x1,17); h_round(x0,x1,29); h_round(x0,x1,16); h_round(x0,x1,24);
    x0 += k2; x1 += k0 + 2u;
    h_round(x0,x1,13); h_round(x0,x1,15); h_round(x0,x1,26); h_round(x0,x1,6);
    x0 += k0; x1 += k1 + 3u;
    h_round(x0,x1,17); h_round(x0,x1,29); h_round(x0,x1,16); h_round(x0,x1,24);
    x0 += k1; x1 += k2 + 4u;
    h_round(x0,x1,13); h_round(x0,x1,15); h_round(x0,x1,26); h_round(x0,x1,6);
    x0 += k2; x1 += k0 + 5u;
    o0 = x0; o1 = x1;
}

// ---------------------------------------------------------------------------
// Device: pipe-balanced threefry. Adds go through IMAD (fma pipe) via the
// opaque-multiplier trick: `one` is a kernel argument ptxas cannot fold, so
// a*one+b must be IMAD. SHF/LOP3 stay on the alu pipe -> ~44 alu / ~48 fma
// ops per normal instead of ~76 alu.
// ---------------------------------------------------------------------------
struct TFKeys {
    uint32_t k0, k1, k2;       // round keys
    uint32_t j1, j2, j3, j4, j5; // k2+1, k0+2, k1+3, k2+4, k0+5 (host-folded)
};

__device__ __forceinline__ uint32_t addi(uint32_t a, uint32_t b, uint32_t one) {
    return a * one + b;        // IMAD -> fma pipe
}

__device__ __forceinline__ void tfr(uint32_t& x0, uint32_t& x1, int r, uint32_t one) {
    x0 = addi(x0, x1, one);                 // IMAD  (fma pipe)
    x1 = __funnelshift_l(x1, x1, r);        // SHF   (alu pipe)
    x1 ^= x0;                               // LOP3  (alu pipe)
}

// Full 20-round threefry on counter (0, c1); returns xor of the two outputs
// (JAX partitionable random_bits combination).
__device__ __forceinline__ uint32_t threefry_xor(const TFKeys k, uint32_t c1, uint32_t one) {
    uint32_t x0 = k.k0;                     // c0 == 0
    uint32_t x1 = addi(c1, k.k1, one);

    tfr(x0,x1,13,one); tfr(x0,x1,15,one); tfr(x0,x1,26,one); tfr(x0,x1,6,one);
    x0 = addi(x0, k.k1, one); x1 = addi(x1, k.j1, one);
    tfr(x0,x1,17,one); tfr(x0,x1,29,one); tfr(x0,x1,16,one); tfr(x0,x1,24,one);
    x0 = addi(x0, k.k2, one); x1 = addi(x1, k.j2, one);
    tfr(x0,x1,13,one); tfr(x0,x1,15,one); tfr(x0,x1,26,one); tfr(x0,x1,6,one);
    x0 = addi(x0, k.k0, one); x1 = addi(x1, k.j3, one);
    tfr(x0,x1,17,one); tfr(x0,x1,29,one); tfr(x0,x1,16,one); tfr(x0,x1,24,one);
    x0 = addi(x0, k.k1, one); x1 = addi(x1, k.j4, one);
    tfr(x0,x1,13,one); tfr(x0,x1,15,one); tfr(x0,x1,26,one); tfr(x0,x1,6,one);
    x0 = addi(x0, k.k2, one); x1 = addi(x1, k.j5, one);

    return x0 ^ x1;
}

// ---------------------------------------------------------------------------
// bits -> p*u where eps = sqrt(2)*(p*u); sqrt(2) is folded by the caller.
// u computation is bit-identical to JAX's path:
//   v = (float)(bits>>9) is exact (23 bits); v*2^-22 == 2f exactly, so the
//   single FMA reproduces RN(2f - 0.99999994f).
// ---------------------------------------------------------------------------
__device__ __forceinline__ float bits_to_pu(uint32_t bits) {
    float v = (float)(bits >> 9);
    float u = __fmaf_rn(v, 0x1p-22f, -0.99999994f);

    float t = __fmul_rn(u, u);
    float w = -__logf(__fadd_rn(1.0f, -t));
    float p;
    if (w < 5.0f) {
        w -= 2.5f;
        p = 2.81022636e-08f;
        p = __fmaf_rn(p, w, 3.43273939e-07f);
        p = __fmaf_rn(p, w, -3.5233877e-06f);
        p = __fmaf_rn(p, w, -4.39150654e-06f);
        p = __fmaf_rn(p, w, 0.00021858087f);
        p = __fmaf_rn(p, w, -0.00125372503f);
        p = __fmaf_rn(p, w, -0.00417768164f);
        p = __fmaf_rn(p, w, 0.246640727f);
        p = __fmaf_rn(p, w, 1.50140941f);
    } else {
        w = __fsqrt_rn(w) - 3.0f;
        p = -0.000200214257f;
        p = __fmaf_rn(p, w, 0.000100950558f);
        p = __fmaf_rn(p, w, 0.00134934322f);
        p = __fmaf_rn(p, w, -0.00367342844f);
        p = __fmaf_rn(p, w, 0.00573950773f);
        p = __fmaf_rn(p, w, -0.0076224613f);
        p = __fmaf_rn(p, w, 0.00943887047f);
        p = __fmaf_rn(p, w, 1.00167406f);
        p = __fmaf_rn(p, w, 2.83297682f);
    }
    return __fmul_rn(p, u);
}

// ---------------------------------------------------------------------------
// One block per output column o; 256 threads stride IN. One mu/sigma load
// feeds 32 samples. counter = s*2^22 + (o*IN + i).
// ---------------------------------------------------------------------------
__global__ void __launch_bounds__(TPB)
bayes_linear_kernel(const float* __restrict__ x,
                    const float* __restrict__ wmu,
                    const float* __restrict__ wsig,
                    const float* __restrict__ bmu,
                    const float* __restrict__ bsig,
                    float* __restrict__ out,
                    TFKeys wk, TFKeys bk,
                    uint32_t one, uint32_t c22 /* == 1<<22, opaque */)
{
    __shared__ float xs[S_][TPB];

    const int o   = blockIdx.x;
    const int tid = threadIdx.x;

    float acc[S_];
#pragma unroll
    for (int s = 0; s < S_; ++s) acc[s] = 0.0f;

    for (int ii = 0; ii < IN_ / TPB; ++ii) {
        const int i = ii * TPB + tid;

        __syncthreads();   // protect xs reuse from previous iteration
#pragma unroll
        for (int s = 0; s < S_; ++s)
            xs[s][tid] = x[s * IN_ + i];
        __syncthreads();

        const float    mu   = wmu[o * IN_ + i];
        const float    sg14 = __fmul_rn(wsig[o * IN_ + i], 1.41421354f);
        const uint32_t base = (uint32_t)(o * IN_ + i);

#pragma unroll 4
        for (int s = 0; s < S_; ++s) {
            const uint32_t c1 = addi((uint32_t)s, base, c22); // s*2^22 + base : IMAD
            const float pu = bits_to_pu(threefry_xor(wk, c1, one));
            acc[s] = __fmaf_rn(__fmaf_rn(sg14, pu, mu), xs[s][tid], acc[s]);
        }
    }

    __syncthreads();
#pragma unroll
    for (int s = 0; s < S_; ++s) xs[s][tid] = acc[s];
    __syncthreads();

    for (int off = TPB / 2; off >= 8; off >>= 1) {
        if (tid < off) {
#pragma unroll
            for (int s = 0; s < S_; ++s)
                xs[s][tid] += xs[s][tid + off];
        }
        __syncthreads();
    }

    if (tid < S_) {
        float tot = 0.0f;
#pragma unroll
        for (int r = 0; r < 8; ++r) tot += xs[tid][r];

        // bias epsilon: idx = s*OUT + o over bkey
        const float pu = bits_to_pu(threefry_xor(bk, (uint32_t)(tid * OUT_ + o), one));
        const float eb = __fmul_rn(1.41421354f, pu);
        out[tid * OUT_ + o] = tot + __fmaf_rn(bsig[o], eb, bmu[o]);
    }
}

// ---------------------------------------------------------------------------
// kernel_launch: host-derived subkeys + opaque constants. Graph-capturable.
// ---------------------------------------------------------------------------
extern "C" void kernel_launch(void* const* d_in, const int* in_sizes, int n_in,
                              void* d_out, int out_size)
{
    const float* x    = (const float*)d_in[0];
    const float* wmu  = (const float*)d_in[1];
    const float* wsig = (const float*)d_in[2];
    const float* bmu  = (const float*)d_in[3];
    const float* bsig = (const float*)d_in[4];
    float* out        = (float*)d_out;

    // jax.random.key(42) -> (0, 42); partitionable split:
    //   wkey = threefry(key,(0,0)), bkey = threefry(key,(0,1))
    uint32_t wk0, wk1, bk0, bk1;
    h_threefry2x32(0u, 42u, 0u, 0u, wk0, wk1);
    h_threefry2x32(0u, 42u, 0u, 1u, bk0, bk1);

    TFKeys wk, bk;
    wk.k0 = wk0; wk.k1 = wk1; wk.k2 = wk0 ^ wk1 ^ 0x1BD11BDAu;
    wk.j1 = wk.k2 + 1u; wk.j2 = wk.k0 + 2u; wk.j3 = wk.k1 + 3u;
    wk.j4 = wk.k2 + 4u; wk.j5 = wk.k0 + 5u;

    bk.k0 = bk0; bk.k1 = bk1; bk.k2 = bk0 ^ bk1 ^ 0x1BD11BDAu;
    bk.j1 = bk.k2 + 1u; bk.j2 = bk.k0 + 2u; bk.j3 = bk.k1 + 3u;
    bk.j4 = bk.k2 + 4u; bk.j5 = bk.k0 + 5u;

    bayes_linear_kernel<<<OUT_, TPB>>>(x, wmu, wsig, bmu, bsig, out,
                                       wk, bk, 1u, 1u << 22);
}

// round 3
// speedup vs baseline: 1.0199x; 1.0032x over previous
#include <cuda_runtime.h>
#include <cstdint>

#define S_   32
#define IN_  2048
#define OUT_ 2048
#define TPB  256

// ---------------------------------------------------------------------------
// Host-side threefry2x32 (subkey derivation for jax.random.key(42) only)
// ---------------------------------------------------------------------------
static inline uint32_t h_rotl32(uint32_t x, int r) {
    return (x << r) | (x >> (32 - r));
}
static inline void h_round(uint32_t& x0, uint32_t& x1, int r) {
    x0 += x1; x1 = h_rotl32(x1, r); x1 ^= x0;
}
static void h_threefry2x32(uint32_t k0, uint32_t k1, uint32_t c0, uint32_t c1,
                           uint32_t& o0, uint32_t& o1)
{
    const uint32_t k2 = k0 ^ k1 ^ 0x1BD11BDAu;
    uint32_t x0 = c0 + k0, x1 = c1 + k1;
    h_round(x0,x1,13); h_round(x0,x1,15); h_round(x0,x1,26); h_round(x0,x1,6);
    x0 += k1; x1 += k2 + 1u;
    h_round(x0,x1,17); h_round(x0,x1,29); h_round(x0,x1,16); h_round(x0,x1,24);
    x0 += k2; x1 += k0 + 2u;
    h_round(x0,x1,13); h_round(x0,x1,15); h_round(x0,x1,26); h_round(x0,x1,6);
    x0 += k0; x1 += k1 + 3u;
    h_round(x0,x1,17); h_round(x0,x1,29); h_round(x0,x1,16); h_round(x0,x1,24);
    x0 += k1; x1 += k2 + 4u;
    h_round(x0,x1,13); h_round(x0,x1,15); h_round(x0,x1,26); h_round(x0,x1,6);
    x0 += k2; x1 += k0 + 5u;
    o0 = x0; o1 = x1;
}

// ---------------------------------------------------------------------------
// Device threefry: adds as IMAD via opaque `one` (fma pipe); SHF/LOP3 on alu.
// ---------------------------------------------------------------------------
struct TFKeys {
    uint32_t k0, k1, k2;
    uint32_t j1, j2, j3, j4, j5;   // k2+1, k0+2, k1+3, k2+4, k0+5
};

__device__ __forceinline__ uint32_t addi(uint32_t a, uint32_t b, uint32_t one) {
    return a * one + b;            // IMAD -> fma pipe
}
__device__ __forceinline__ void tfr(uint32_t& x0, uint32_t& x1, int r, uint32_t one) {
    x0 = addi(x0, x1, one);
    x1 = __funnelshift_l(x1, x1, r);
    x1 ^= x0;
}
__device__ __forceinline__ uint32_t threefry_xor(const TFKeys k, uint32_t c1, uint32_t one) {
    uint32_t x0 = k.k0;            // c0 == 0
    uint32_t x1 = addi(c1, k.k1, one);

    tfr(x0,x1,13,one); tfr(x0,x1,15,one); tfr(x0,x1,26,one); tfr(x0,x1,6,one);
    x0 = addi(x0, k.k1, one); x1 = addi(x1, k.j1, one);
    tfr(x0,x1,17,one); tfr(x0,x1,29,one); tfr(x0,x1,16,one); tfr(x0,x1,24,one);
    x0 = addi(x0, k.k2, one); x1 = addi(x1, k.j2, one);
    tfr(x0,x1,13,one); tfr(x0,x1,15,one); tfr(x0,x1,26,one); tfr(x0,x1,6,one);
    x0 = addi(x0, k.k0, one); x1 = addi(x1, k.j3, one);
    tfr(x0,x1,17,one); tfr(x0,x1,29,one); tfr(x0,x1,16,one); tfr(x0,x1,24,one);
    x0 = addi(x0, k.k1, one); x1 = addi(x1, k.j4, one);
    tfr(x0,x1,13,one); tfr(x0,x1,15,one); tfr(x0,x1,26,one); tfr(x0,x1,6,one);
    x0 = addi(x0, k.k2, one); x1 = addi(x1, k.j5, one);

    return x0 ^ x1;
}

// ---------------------------------------------------------------------------
// bits -> p*u  (eps = sqrt(2)*p*u; sqrt(2) folded by caller).
//   u  = fma((float)(bits>>9), 2^-22, -0.99999994f)   (bit-exact vs JAX path)
//   l  = log2(1-u*u)  [MUFU.LG2]
//   wc = fma(l, -ln2, -2.5)  == w - 2.5
// Central Giles poly always; rare tail (wc >= 2.5, P=0.33%/lane) as a real
// divergent branch so ~90% of warps never execute the 17-instr tail arm.
// ---------------------------------------------------------------------------
__device__ __forceinline__ float bits_to_pu(uint32_t bits) {
    float v = (float)(bits >> 9);
    float u = __fmaf_rn(v, 0x1p-22f, -0.99999994f);

    float t = __fmul_rn(u, u);
    float y = __fadd_rn(1.0f, -t);
    float l = __log2f(y);
    float wc = __fmaf_rn(l, -0.69314718f, -2.5f);   // w - 2.5

    float p;
    p = 2.81022636e-08f;
    p = __fmaf_rn(p, wc, 3.43273939e-07f);
    p = __fmaf_rn(p, wc, -3.5233877e-06f);
    p = __fmaf_rn(p, wc, -4.39150654e-06f);
    p = __fmaf_rn(p, wc, 0.00021858087f);
    p = __fmaf_rn(p, wc, -0.00125372503f);
    p = __fmaf_rn(p, wc, -0.00417768164f);
    p = __fmaf_rn(p, wc, 0.246640727f);
    p = __fmaf_rn(p, wc, 1.50140941f);

    if (wc >= 2.5f) {   // rare tail: |u| > 0.99666
        float w  = __fmul_rn(l, -0.69314718f);
        float ws = __fsqrt_rn(w) - 3.0f;
        p = -0.000200214257f;
        p = __fmaf_rn(p, ws, 0.000100950558f);
        p = __fmaf_rn(p, ws, 0.00134934322f);
        p = __fmaf_rn(p, ws, -0.00367342844f);
        p = __fmaf_rn(p, ws, 0.00573950773f);
        p = __fmaf_rn(p, ws, -0.0076224613f);
        p = __fmaf_rn(p, ws, 0.00943887047f);
        p = __fmaf_rn(p, ws, 1.00167406f);
        p = __fmaf_rn(p, ws, 2.83297682f);
    }
    return __fmul_rn(p, u);
}

// ---------------------------------------------------------------------------
// One block per output column o; 256 threads stride IN. One mu/sigma load
// feeds 32 samples. counter = s*2^22 + (o*IN + i).
// ---------------------------------------------------------------------------
__global__ void __launch_bounds__(TPB)
bayes_linear_kernel(const float* __restrict__ x,
                    const float* __restrict__ wmu,
                    const float* __restrict__ wsig,
                    const float* __restrict__ bmu,
                    const float* __restrict__ bsig,
                    float* __restrict__ out,
                    TFKeys wk, TFKeys bk,
                    uint32_t one, uint32_t c22 /* == 1<<22, opaque */)
{
    __shared__ float xs[S_][TPB];

    const int o   = blockIdx.x;
    const int tid = threadIdx.x;

    float acc[S_];
#pragma unroll
    for (int s = 0; s < S_; ++s) acc[s] = 0.0f;

    for (int ii = 0; ii < IN_ / TPB; ++ii) {
        const int i = ii * TPB + tid;

        __syncthreads();   // protect xs reuse from previous iteration
#pragma unroll
        for (int s = 0; s < S_; ++s)
            xs[s][tid] = x[s * IN_ + i];
        __syncthreads();

        const float    mu   = wmu[o * IN_ + i];
        const float    sg14 = __fmul_rn(wsig[o * IN_ + i], 1.41421354f);
        const uint32_t base = (uint32_t)(o * IN_ + i);

#pragma unroll 4
        for (int s = 0; s < S_; ++s) {
            const uint32_t c1 = addi((uint32_t)s, base, c22); // s*2^22 + base
            const float pu = bits_to_pu(threefry_xor(wk, c1, one));
            acc[s] = __fmaf_rn(__fmaf_rn(sg14, pu, mu), xs[s][tid], acc[s]);
        }
    }

    __syncthreads();
#pragma unroll
    for (int s = 0; s < S_; ++s) xs[s][tid] = acc[s];
    __syncthreads();

    for (int off = TPB / 2; off >= 8; off >>= 1) {
        if (tid < off) {
#pragma unroll
            for (int s = 0; s < S_; ++s)
                xs[s][tid] += xs[s][tid + off];
        }
        __syncthreads();
    }

    if (tid < S_) {
        float tot = 0.0f;
#pragma unroll
        for (int r = 0; r < 8; ++r) tot += xs[tid][r];

        // bias epsilon: idx = s*OUT + o over bkey
        const float pu = bits_to_pu(threefry_xor(bk, (uint32_t)(tid * OUT_ + o), one));
        const float eb = __fmul_rn(1.41421354f, pu);
        out[tid * OUT_ + o] = tot + __fmaf_rn(bsig[o], eb, bmu[o]);
    }
}

// ---------------------------------------------------------------------------
extern "C" void kernel_launch(void* const* d_in, const int* in_sizes, int n_in,
                              void* d_out, int out_size)
{
    const float* x    = (const float*)d_in[0];
    const float* wmu  = (const float*)d_in[1];
    const float* wsig = (const float*)d_in[2];
    const float* bmu  = (const float*)d_in[3];
    const float* bsig = (const float*)d_in[4];
    float* out        = (float*)d_out;

    uint32_t wk0, wk1, bk0, bk1;
    h_threefry2x32(0u, 42u, 0u, 0u, wk0, wk1);
    h_threefry2x32(0u, 42u, 0u, 1u, bk0, bk1);

    TFKeys wk, bk;
    wk.k0 = wk0; wk.k1 = wk1; wk.k2 = wk0 ^ wk1 ^ 0x1BD11BDAu;
    wk.j1 = wk.k2 + 1u; wk.j2 = wk.k0 + 2u; wk.j3 = wk.k1 + 3u;
    wk.j4 = wk.k2 + 4u; wk.j5 = wk.k0 + 5u;

    bk.k0 = bk0; bk.k1 = bk1; bk.k2 = bk0 ^ bk1 ^ 0x1BD11BDAu;
    bk.j1 = bk.k2 + 1u; bk.j2 = bk.k0 + 2u; bk.j3 = bk.k1 + 3u;
    bk.j4 = bk.k2 + 4u; bk.j5 = bk.k0 + 5u;

    bayes_linear_kernel<<<OUT_, TPB>>>(x, wmu, wsig, bmu, bsig, out,
                                       wk, bk, 1u, 1u << 22);
}

// round 4
// speedup vs baseline: 1.1229x; 1.1009x over previous
#include <cuda_runtime.h>
#include <cstdint>

#define S_   32
#define IN_  2048
#define OUT_ 2048
#define TPB  256
#define SGRP 8                    // samples per register group
#define NGRP (S_ / SGRP)

// ---------------------------------------------------------------------------
// Host-side threefry2x32 (subkey derivation for jax.random.key(42) only)
// ---------------------------------------------------------------------------
static inline uint32_t h_rotl32(uint32_t x, int r) {
    return (x << r) | (x >> (32 - r));
}
static inline void h_round(uint32_t& x0, uint32_t& x1, int r) {
    x0 += x1; x1 = h_rotl32(x1, r); x1 ^= x0;
}
static void h_threefry2x32(uint32_t k0, uint32_t k1, uint32_t c0, uint32_t c1,
                           uint32_t& o0, uint32_t& o1)
{
    const uint32_t k2 = k0 ^ k1 ^ 0x1BD11BDAu;
    uint32_t x0 = c0 + k0, x1 = c1 + k1;
    h_round(x0,x1,13); h_round(x0,x1,15); h_round(x0,x1,26); h_round(x0,x1,6);
    x0 += k1; x1 += k2 + 1u;
    h_round(x0,x1,17); h_round(x0,x1,29); h_round(x0,x1,16); h_round(x0,x1,24);
    x0 += k2; x1 += k0 + 2u;
    h_round(x0,x1,13); h_round(x0,x1,15); h_round(x0,x1,26); h_round(x0,x1,6);
    x0 += k0; x1 += k1 + 3u;
    h_round(x0,x1,17); h_round(x0,x1,29); h_round(x0,x1,16); h_round(x0,x1,24);
    x0 += k1; x1 += k2 + 4u;
    h_round(x0,x1,13); h_round(x0,x1,15); h_round(x0,x1,26); h_round(x0,x1,6);
    x0 += k2; x1 += k0 + 5u;
    o0 = x0; o1 = x1;
}

// ---------------------------------------------------------------------------
// Device threefry: adds as IMAD via opaque `one` (fma pipe); SHF/LOP3 on alu.
// Takes x1 with k1 already folded in by the caller (x1 = c1 + k1).
// ---------------------------------------------------------------------------
struct TFKeys {
    uint32_t k0, k1, k2;
    uint32_t j1, j2, j3, j4, j5;   // k2+1, k0+2, k1+3, k2+4, k0+5
};

__device__ __forceinline__ uint32_t addi(uint32_t a, uint32_t b, uint32_t one) {
    return a * one + b;            // IMAD -> fma pipe
}
__device__ __forceinline__ void tfr(uint32_t& x0, uint32_t& x1, int r, uint32_t one) {
    x0 = addi(x0, x1, one);
    x1 = __funnelshift_l(x1, x1, r);
    x1 ^= x0;
}
__device__ __forceinline__ uint32_t threefry_from_x1(const TFKeys k, uint32_t x1, uint32_t one) {
    uint32_t x0 = k.k0;            // c0 == 0

    tfr(x0,x1,13,one); tfr(x0,x1,15,one); tfr(x0,x1,26,one); tfr(x0,x1,6,one);
    x0 = addi(x0, k.k1, one); x1 = addi(x1, k.j1, one);
    tfr(x0,x1,17,one); tfr(x0,x1,29,one); tfr(x0,x1,16,one); tfr(x0,x1,24,one);
    x0 = addi(x0, k.k2, one); x1 = addi(x1, k.j2, one);
    tfr(x0,x1,13,one); tfr(x0,x1,15,one); tfr(x0,x1,26,one); tfr(x0,x1,6,one);
    x0 = addi(x0, k.k0, one); x1 = addi(x1, k.j3, one);
    tfr(x0,x1,17,one); tfr(x0,x1,29,one); tfr(x0,x1,16,one); tfr(x0,x1,24,one);
    x0 = addi(x0, k.k1, one); x1 = addi(x1, k.j4, one);
    tfr(x0,x1,13,one); tfr(x0,x1,15,one); tfr(x0,x1,26,one); tfr(x0,x1,6,one);
    x0 = addi(x0, k.k2, one); x1 = addi(x1, k.j5, one);

    return x0 ^ x1;
}

// ---------------------------------------------------------------------------
// bits -> eps = sqrt(2)*erfinv(u).  sqrt(2) is folded into the polynomial
// coefficients (error ~1ulp/coeff, well inside the ~1e-4 budget).
//   u  = fma((float)(bits>>9), 2^-22, -0.99999994f)
//   l  = log2(1-u^2)  [MUFU.LG2];  wc = fma(l, -ln2, -2.5) == w-2.5
// Central Giles poly always; rare tail (P=0.33%/lane) as divergent branch.
// ---------------------------------------------------------------------------
__device__ __forceinline__ float bits_to_eps(uint32_t bits) {
    float v = (float)(bits >> 9);
    float u = __fmaf_rn(v, 0x1p-22f, -0.99999994f);

    float t = __fmul_rn(u, u);
    float y = __fadd_rn(1.0f, -t);
    float l = __log2f(y);
    float wc = __fmaf_rn(l, -0.69314718f, -2.5f);   // w - 2.5

    float p;
    p = 3.9740742e-08f;
    p = __fmaf_rn(p, wc, 4.8546264e-07f);
    p = __fmaf_rn(p, wc, -4.9828285e-06f);
    p = __fmaf_rn(p, wc, -6.2105203e-06f);
    p = __fmaf_rn(p, wc, 3.0911997e-04f);
    p = __fmaf_rn(p, wc, -1.7730364e-03f);
    p = __fmaf_rn(p, wc, -5.9081367e-03f);
    p = __fmaf_rn(p, wc, 3.4880266e-01f);
    p = __fmaf_rn(p, wc, 2.1233135e+00f);

    if (wc >= 2.5f) {   // rare tail: |u| > 0.99666
        float w  = __fmul_rn(l, -0.69314718f);
        float ws = __fsqrt_rn(w) - 3.0f;
        p = -2.8314684e-04f;
        p = __fmaf_rn(p, ws, 1.4276590e-04f);
        p = __fmaf_rn(p, ws, 1.9082523e-03f);
        p = __fmaf_rn(p, ws, -5.1950109e-03f);
        p = __fmaf_rn(p, ws, 8.1168911e-03f);
        p = __fmaf_rn(p, ws, -1.0779785e-02f);
        p = __fmaf_rn(p, ws, 1.3348580e-02f);
        p = __fmaf_rn(p, ws, 1.4165810e+00f);
        p = __fmaf_rn(p, ws, 4.0064341e+00f);
    }
    return __fmul_rn(p, u);
}

// ---------------------------------------------------------------------------
// One block per output column o. Outer loop: 4 groups of 8 samples (acc[8]
// in registers, fully unrolled). Inner loop: i strided by 256 threads.
// No smem in the mainloop; warp-shuffle reduction at group end.
// counter = s*2^22 + (o*IN + i);  x1-init has k1 prefolded.
// ---------------------------------------------------------------------------
__global__ void __launch_bounds__(TPB)
bayes_linear_kernel(const float* __restrict__ x,
                    const float* __restrict__ wmu,
                    const float* __restrict__ wsig,
                    const float* __restrict__ bmu,
                    const float* __restrict__ bsig,
                    float* __restrict__ out,
                    TFKeys wk, TFKeys bk,
                    uint32_t one, uint32_t c22 /* == 1<<22, opaque */)
{
    __shared__ float red[S_][9];   // [sample][warp] partials (pad to 9)

    const int o    = blockIdx.x;
    const int tid  = threadIdx.x;
    const int lane = tid & 31;
    const int warp = tid >> 5;
    const uint32_t base_o = (uint32_t)o * (uint32_t)IN_;

#pragma unroll 1
    for (int g = 0; g < NGRP; ++g) {
        const int sbase = g * SGRP;

        float acc[SGRP];
#pragma unroll
        for (int j = 0; j < SGRP; ++j) acc[j] = 0.0f;

#pragma unroll 1
        for (int ii = 0; ii < IN_ / TPB; ++ii) {
            const int i = ii * TPB + tid;
            const float mu = wmu[base_o + i];
            const float sg = wsig[base_o + i];
            const float* xp = x + (size_t)sbase * IN_ + i;

            // x1 init for j=0: sbase*2^22 + (base + i) + k1 ; per-j adds j*2^22
            const uint32_t cb = addi((uint32_t)sbase,
                                     base_o + (uint32_t)i + wk.k1, c22);

#pragma unroll
            for (int j = 0; j < SGRP; ++j) {
                const uint32_t bits = threefry_from_x1(wk, cb + ((uint32_t)j << 22), one);
                const float eps = bits_to_eps(bits);
                acc[j] = __fmaf_rn(__fmaf_rn(sg, eps, mu), xp[j * IN_], acc[j]);
            }
        }

        // warp butterfly reduction; lane 0 stores the 8 partials
#pragma unroll
        for (int j = 0; j < SGRP; ++j) {
#pragma unroll
            for (int m = 16; m >= 1; m >>= 1)
                acc[j] += __shfl_xor_sync(0xffffffffu, acc[j], m);
        }
        if (lane == 0) {
#pragma unroll
            for (int j = 0; j < SGRP; ++j)
                red[sbase + j][warp] = acc[j];
        }
    }

    __syncthreads();

    if (tid < S_) {
        float tot = 0.0f;
#pragma unroll
        for (int w = 0; w < TPB / 32; ++w) tot += red[tid][w];

        // bias epsilon: counter = s*OUT + o over bkey (sqrt2 already folded)
        const uint32_t c1 = (uint32_t)(tid * OUT_ + o);
        const float eb = bits_to_eps(threefry_from_x1(bk, c1 + bk.k1, one));
        out[tid * OUT_ + o] = tot + __fmaf_rn(bsig[o], eb, bmu[o]);
    }
}

// ---------------------------------------------------------------------------
extern "C" void kernel_launch(void* const* d_in, const int* in_sizes, int n_in,
                              void* d_out, int out_size)
{
    const float* x    = (const float*)d_in[0];
    const float* wmu  = (const float*)d_in[1];
    const float* wsig = (const float*)d_in[2];
    const float* bmu  = (const float*)d_in[3];
    const float* bsig = (const float*)d_in[4];
    float* out        = (float*)d_out;

    uint32_t wk0, wk1, bk0, bk1;
    h_threefry2x32(0u, 42u, 0u, 0u, wk0, wk1);
    h_threefry2x32(0u, 42u, 0u, 1u, bk0, bk1);

    TFKeys wk, bk;
    wk.k0 = wk0; wk.k1 = wk1; wk.k2 = wk0 ^ wk1 ^ 0x1BD11BDAu;
    wk.j1 = wk.k2 + 1u; wk.j2 = wk.k0 + 2u; wk.j3 = wk.k1 + 3u;
    wk.j4 = wk.k2 + 4u; wk.j5 = wk.k0 + 5u;

    bk.k0 = bk0; bk.k1 = bk1; bk.k2 = bk0 ^ bk1 ^ 0x1BD11BDAu;
    bk.j1 = bk.k2 + 1u; bk.j2 = bk.k0 + 2u; bk.j3 = bk.k1 + 3u;
    bk.j4 = bk.k2 + 4u; bk.j5 = bk.k0 + 5u;

    bayes_linear_kernel<<<OUT_, TPB>>>(x, wmu, wsig, bmu, bsig, out,
                                       wk, bk, 1u, 1u << 22);
}

// round 5
// speedup vs baseline: 1.1245x; 1.0014x over previous
#include <cuda_runtime.h>
#include <cstdint>

#define S_   32
#define IN_  2048
#define OUT_ 2048
#define TPB  256
#define SGRP 8                    // samples per register group
#define NGRP (S_ / SGRP)

// ---------------------------------------------------------------------------
// Host-side threefry2x32 (subkey derivation for jax.random.key(42) only)
// ---------------------------------------------------------------------------
static inline uint32_t h_rotl32(uint32_t x, int r) {
    return (x << r) | (x >> (32 - r));
}
static inline void h_round(uint32_t& x0, uint32_t& x1, int r) {
    x0 += x1; x1 = h_rotl32(x1, r); x1 ^= x0;
}
static void h_threefry2x32(uint32_t k0, uint32_t k1, uint32_t c0, uint32_t c1,
                           uint32_t& o0, uint32_t& o1)
{
    const uint32_t k2 = k0 ^ k1 ^ 0x1BD11BDAu;
    uint32_t x0 = c0 + k0, x1 = c1 + k1;
    h_round(x0,x1,13); h_round(x0,x1,15); h_round(x0,x1,26); h_round(x0,x1,6);
    x0 += k1; x1 += k2 + 1u;
    h_round(x0,x1,17); h_round(x0,x1,29); h_round(x0,x1,16); h_round(x0,x1,24);
    x0 += k2; x1 += k0 + 2u;
    h_round(x0,x1,13); h_round(x0,x1,15); h_round(x0,x1,26); h_round(x0,x1,6);
    x0 += k0; x1 += k1 + 3u;
    h_round(x0,x1,17); h_round(x0,x1,29); h_round(x0,x1,16); h_round(x0,x1,24);
    x0 += k1; x1 += k2 + 4u;
    h_round(x0,x1,13); h_round(x0,x1,15); h_round(x0,x1,26); h_round(x0,x1,6);
    x0 += k2; x1 += k0 + 5u;
    o0 = x0; o1 = x1;
}

// ---------------------------------------------------------------------------
// Device threefry. Round structure tuned for sm_100 pipes:
//   x0 += x1            -> IMAD (fma pipe, opaque `one`)
//   rotl(x1, R)         -> IMAD.WIDE.U32 x1 * 2^R (fma pipe): hi=x>>32-R, lo=x<<R
//   x1 = (lo|hi) ^ x0   -> single LOP3 (alu pipe)
// Only LOP3s remain on the half-rate alu pipe.
// ---------------------------------------------------------------------------
struct TFKeys {
    uint32_t k0, k1, k2;
    uint32_t j1, j2, j3, j4, j5;   // k2+1, k0+2, k1+3, k2+4, k0+5
};

__device__ __forceinline__ uint32_t addi(uint32_t a, uint32_t b, uint32_t one) {
    return a * one + b;            // IMAD -> fma pipe
}

template<int R>
__device__ __forceinline__ void tfr(uint32_t& x0, uint32_t& x1, uint32_t one) {
    x0 = addi(x0, x1, one);                                  // IMAD
    const uint64_t p = (uint64_t)x1 * (uint64_t)(1u << R);   // IMAD.WIDE imm
    x1 = (((uint32_t)p) | ((uint32_t)(p >> 32))) ^ x0;       // LOP3 (a|b)^c
}

__device__ __forceinline__ uint32_t threefry_from_x1(const TFKeys k, uint32_t x1, uint32_t one) {
    uint32_t x0 = k.k0;            // c0 == 0

    tfr<13>(x0,x1,one); tfr<15>(x0,x1,one); tfr<26>(x0,x1,one); tfr<6>(x0,x1,one);
    x0 = addi(x0, k.k1, one); x1 = addi(x1, k.j1, one);
    tfr<17>(x0,x1,one); tfr<29>(x0,x1,one); tfr<16>(x0,x1,one); tfr<24>(x0,x1,one);
    x0 = addi(x0, k.k2, one); x1 = addi(x1, k.j2, one);
    tfr<13>(x0,x1,one); tfr<15>(x0,x1,one); tfr<26>(x0,x1,one); tfr<6>(x0,x1,one);
    x0 = addi(x0, k.k0, one); x1 = addi(x1, k.j3, one);
    tfr<17>(x0,x1,one); tfr<29>(x0,x1,one); tfr<16>(x0,x1,one); tfr<24>(x0,x1,one);
    x0 = addi(x0, k.k1, one); x1 = addi(x1, k.j4, one);
    tfr<13>(x0,x1,one); tfr<15>(x0,x1,one); tfr<26>(x0,x1,one); tfr<6>(x0,x1,one);
    x0 = addi(x0, k.k2, one); x1 = addi(x1, k.j5, one);

    return x0 ^ x1;
}

// ---------------------------------------------------------------------------
// bits -> eps = sqrt(2)*erfinv(u).  sqrt(2) folded into the coefficients.
//   u  = fma((float)(bits>>9), 2^-22, -0.99999994f)   (bit-exact vs JAX)
//   l  = log2(1-u^2)  [MUFU.LG2];  wc = fma(l, -ln2, -2.5) == w-2.5
// Central Giles poly always; rare tail (P=0.33%/lane) as divergent branch.
// ---------------------------------------------------------------------------
__device__ __forceinline__ float bits_to_eps(uint32_t bits) {
    float v = (float)(bits >> 9);
    float u = __fmaf_rn(v, 0x1p-22f, -0.99999994f);

    float t = __fmul_rn(u, u);
    float y = __fadd_rn(1.0f, -t);
    float l = __log2f(y);
    float wc = __fmaf_rn(l, -0.69314718f, -2.5f);   // w - 2.5

    float p;
    p = 3.9740742e-08f;
    p = __fmaf_rn(p, wc, 4.8546264e-07f);
    p = __fmaf_rn(p, wc, -4.9828285e-06f);
    p = __fmaf_rn(p, wc, -6.2105203e-06f);
    p = __fmaf_rn(p, wc, 3.0911997e-04f);
    p = __fmaf_rn(p, wc, -1.7730364e-03f);
    p = __fmaf_rn(p, wc, -5.9081367e-03f);
    p = __fmaf_rn(p, wc, 3.4880266e-01f);
    p = __fmaf_rn(p, wc, 2.1233135e+00f);

    if (wc >= 2.5f) {   // rare tail: |u| > 0.99666
        float w  = __fmul_rn(l, -0.69314718f);
        float ws = __fsqrt_rn(w) - 3.0f;
        p = -2.8314684e-04f;
        p = __fmaf_rn(p, ws, 1.4276590e-04f);
        p = __fmaf_rn(p, ws, 1.9082523e-03f);
        p = __fmaf_rn(p, ws, -5.1950109e-03f);
        p = __fmaf_rn(p, ws, 8.1168911e-03f);
        p = __fmaf_rn(p, ws, -1.0779785e-02f);
        p = __fmaf_rn(p, ws, 1.3348580e-02f);
        p = __fmaf_rn(p, ws, 1.4165810e+00f);
        p = __fmaf_rn(p, ws, 4.0064341e+00f);
    }
    return __fmul_rn(p, u);
}

// ---------------------------------------------------------------------------
// One block per output column o. Outer loop: 4 groups of 8 samples (acc[8]
// in registers, fully unrolled). Inner loop: i strided by 256 threads.
// No smem in the mainloop; warp-shuffle reduction at group end.
// counter = s*2^22 + (o*IN + i);  x1-init has k1 prefolded.
// ---------------------------------------------------------------------------
__global__ void __launch_bounds__(TPB)
bayes_linear_kernel(const float* __restrict__ x,
                    const float* __restrict__ wmu,
                    const float* __restrict__ wsig,
                    const float* __restrict__ bmu,
                    const float* __restrict__ bsig,
                    float* __restrict__ out,
                    TFKeys wk, TFKeys bk,
                    uint32_t one, uint32_t c22 /* == 1<<22, opaque */)
{
    __shared__ float red[S_][9];   // [sample][warp] partials (pad to 9)

    const int o    = blockIdx.x;
    const int tid  = threadIdx.x;
    const int lane = tid & 31;
    const int warp = tid >> 5;
    const uint32_t base_o = (uint32_t)o * (uint32_t)IN_;

#pragma unroll 1
    for (int g = 0; g < NGRP; ++g) {
        const int sbase = g * SGRP;

        float acc[SGRP];
#pragma unroll
        for (int j = 0; j < SGRP; ++j) acc[j] = 0.0f;

#pragma unroll 1
        for (int ii = 0; ii < IN_ / TPB; ++ii) {
            const int i = ii * TPB + tid;
            const float mu = wmu[base_o + i];
            const float sg = wsig[base_o + i];
            const float* xp = x + (size_t)sbase * IN_ + i;

            // x1 init for j=0: sbase*2^22 + (base + i) + k1 ; per-j adds j*2^22
            const uint32_t cb = addi((uint32_t)sbase,
                                     base_o + (uint32_t)i + wk.k1, c22);

#pragma unroll
            for (int j = 0; j < SGRP; ++j) {
                const uint32_t bits = threefry_from_x1(wk, cb + ((uint32_t)j << 22), one);
                const float eps = bits_to_eps(bits);
                acc[j] = __fmaf_rn(__fmaf_rn(sg, eps, mu), xp[j * IN_], acc[j]);
            }
        }

        // warp butterfly reduction; lane 0 stores the 8 partials
#pragma unroll
        for (int j = 0; j < SGRP; ++j) {
#pragma unroll
            for (int m = 16; m >= 1; m >>= 1)
                acc[j] += __shfl_xor_sync(0xffffffffu, acc[j], m);
        }
        if (lane == 0) {
#pragma unroll
            for (int j = 0; j < SGRP; ++j)
                red[sbase + j][warp] = acc[j];
        }
    }

    __syncthreads();

    if (tid < S_) {
        float tot = 0.0f;
#pragma unroll
        for (int w = 0; w < TPB / 32; ++w) tot += red[tid][w];

        // bias epsilon: counter = s*OUT + o over bkey (sqrt2 already folded)
        const uint32_t c1 = (uint32_t)(tid * OUT_ + o);
        const float eb = bits_to_eps(threefry_from_x1(bk, c1 + bk.k1, one));
        out[tid * OUT_ + o] = tot + __fmaf_rn(bsig[o], eb, bmu[o]);
    }
}

// ---------------------------------------------------------------------------
extern "C" void kernel_launch(void* const* d_in, const int* in_sizes, int n_in,
                              void* d_out, int out_size)
{
    const float* x    = (const float*)d_in[0];
    const float* wmu  = (const float*)d_in[1];
    const float* wsig = (const float*)d_in[2];
    const float* bmu  = (const float*)d_in[3];
    const float* bsig = (const float*)d_in[4];
    float* out        = (float*)d_out;

    uint32_t wk0, wk1, bk0, bk1;
    h_threefry2x32(0u, 42u, 0u, 0u, wk0, wk1);
    h_threefry2x32(0u, 42u, 0u, 1u, bk0, bk1);

    TFKeys wk, bk;
    wk.k0 = wk0; wk.k1 = wk1; wk.k2 = wk0 ^ wk1 ^ 0x1BD11BDAu;
    wk.j1 = wk.k2 + 1u; wk.j2 = wk.k0 + 2u; wk.j3 = wk.k1 + 3u;
    wk.j4 = wk.k2 + 4u; wk.j5 = wk.k0 + 5u;

    bk.k0 = bk0; bk.k1 = bk1; bk.k2 = bk0 ^ bk1 ^ 0x1BD11BDAu;
    bk.j1 = bk.k2 + 1u; bk.j2 = bk.k0 + 2u; bk.j3 = bk.k1 + 3u;
    bk.j4 = bk.k2 + 4u; bk.j5 = bk.k0 + 5u;

    bayes_linear_kernel<<<OUT_, TPB>>>(x, wmu, wsig, bmu, bsig, out,
                                       wk, bk, 1u, 1u << 22);
}